// round 8
// baseline (speedup 1.0000x reference)
#include <cuda_runtime.h>
#include <math.h>

#define NN 50000
#define EE 800000
#define ET 850000          // edges + self loops
#define F_IN 512
#define F1 128             // H1*C1
#define H1n 8
#define C1n 16
#define F2 40              // H2*C2 = num classes
#define NEG_SLOPE 0.2f

// ---------------- static scratch (no allocation allowed) ----------------
__device__ float g_h1 [(size_t)NN * F1];   // x@W1
__device__ float g_h1b[(size_t)NN * F1];   // elu(layer1 out)
__device__ float g_h2 [(size_t)NN * F2];   // h1b@W2
__device__ float g_as1[NN * H1n], g_ad1[NN * H1n];
__device__ float g_as2[NN],        g_ad2[NN];
__device__ int   g_deg[NN], g_fill[NN];
__device__ int   g_rowptr[NN + 1];
__device__ int   g_col[ET];
__device__ int   g_is64;   // 1 if edge_index is int64, 0 if int32

// ---------------- dtype probe ----------------
// JAX with x64 disabled silently downcasts jnp.int64 -> int32. Detect on
// device: genuine int64 indices are all < NN; int32 data read as u64 pairs
// two values (lo | hi<<32) and hi != 0 with prob 1 - 1/NN per entry.
__global__ void k_detect(const void* __restrict__ ei) {
    if (threadIdx.x != 0 || blockIdx.x != 0) return;
    const unsigned long long* p = (const unsigned long long*)ei;
    int is64 = 1;
    for (int i = 0; i < 256; i++) {
        if (p[i] >= (unsigned long long)NN) { is64 = 0; break; }
    }
    g_is64 = is64;
}

__device__ __forceinline__ int load_idx(const void* ei, int i) {
    if (g_is64) return (int)((const long long*)ei)[i];
    return ((const int*)ei)[i];
}

// ---------------- CSR build ----------------
__global__ void k_zero_deg() {
    int i = blockIdx.x * blockDim.x + threadIdx.x;
    if (i < NN) g_deg[i] = 0;
}

__global__ void k_hist(const void* __restrict__ ei) {
    int e = blockIdx.x * blockDim.x + threadIdx.x;
    if (e >= ET) return;
    int d;
    if (e < EE) d = load_idx(ei, EE + e);
    else        d = e - EE;          // self loop
    atomicAdd(&g_deg[d], 1);
}

__global__ void k_scan() {
    __shared__ int sums[1024];
    int t = threadIdx.x;
    const int chunk = (NN + 1023) / 1024;   // 49
    int start = t * chunk;
    int end   = min(start + chunk, NN);
    int s = 0;
    for (int i = start; i < end; i++) s += g_deg[i];
    sums[t] = s;
    __syncthreads();
    // Hillis-Steele inclusive scan
    for (int off = 1; off < 1024; off <<= 1) {
        int v = (t >= off) ? sums[t - off] : 0;
        __syncthreads();
        sums[t] += v;
        __syncthreads();
    }
    int prefix = (t == 0) ? 0 : sums[t - 1];
    for (int i = start; i < end; i++) {
        g_rowptr[i] = prefix;
        prefix += g_deg[i];
        g_fill[i] = 0;
    }
    if (t == 1023) g_rowptr[NN] = sums[1023];
}

__global__ void k_scatter(const void* __restrict__ ei) {
    int e = blockIdx.x * blockDim.x + threadIdx.x;
    if (e >= ET) return;
    int s, d;
    if (e < EE) { s = load_idx(ei, e); d = load_idx(ei, EE + e); }
    else        { s = d = e - EE; }
    int pos = g_rowptr[d] + atomicAdd(&g_fill[d], 1);
    g_col[pos] = s;
}

// ---------------- GEMM1: h1 = x @ W1   (50000x512 @ 512x128) ----------------
// BM=128, BN=128 (full), BK=16, 256 threads, 8x8 microtile
__global__ void k_gemm1(const float* __restrict__ x, const float* __restrict__ W1) {
    __shared__ float As[16][128];
    __shared__ float Bs[16][128];
    const int tid = threadIdx.x;
    const int m0  = blockIdx.x * 128;
    const int tm  = (tid / 16) * 8;
    const int tn  = (tid % 16) * 8;
    float acc[8][8];
    #pragma unroll
    for (int i = 0; i < 8; i++)
        #pragma unroll
        for (int j = 0; j < 8; j++) acc[i][j] = 0.f;

    for (int k0 = 0; k0 < F_IN; k0 += 16) {
        // A tile: 128 rows x 16 cols = 512 float4, 2 per thread (transposed store)
        #pragma unroll
        for (int i = 0; i < 2; i++) {
            int li  = tid * 2 + i;         // 0..511
            int row = li >> 2;             // 0..127
            int c4  = li & 3;              // which float4 of the 16 cols
            float4 v = make_float4(0.f, 0.f, 0.f, 0.f);
            int gm = m0 + row;
            if (gm < NN)
                v = *(const float4*)&x[(size_t)gm * F_IN + k0 + c4 * 4];
            As[c4 * 4 + 0][row] = v.x;
            As[c4 * 4 + 1][row] = v.y;
            As[c4 * 4 + 2][row] = v.z;
            As[c4 * 4 + 3][row] = v.w;
        }
        // B tile: 16 rows x 128 cols = 512 float4, 2 per thread
        #pragma unroll
        for (int i = 0; i < 2; i++) {
            int li  = tid * 2 + i;
            int row = li >> 5;             // 0..15
            int c4  = li & 31;             // 0..31
            float4 v = *(const float4*)&W1[(size_t)(k0 + row) * F1 + c4 * 4];
            *(float4*)&Bs[row][c4 * 4] = v;
        }
        __syncthreads();
        #pragma unroll
        for (int k = 0; k < 16; k++) {
            float4 a0 = *(const float4*)&As[k][tm];
            float4 a1 = *(const float4*)&As[k][tm + 4];
            float4 b0 = *(const float4*)&Bs[k][tn];
            float4 b1 = *(const float4*)&Bs[k][tn + 4];
            float a[8] = {a0.x, a0.y, a0.z, a0.w, a1.x, a1.y, a1.z, a1.w};
            float b[8] = {b0.x, b0.y, b0.z, b0.w, b1.x, b1.y, b1.z, b1.w};
            #pragma unroll
            for (int i = 0; i < 8; i++)
                #pragma unroll
                for (int j = 0; j < 8; j++)
                    acc[i][j] = fmaf(a[i], b[j], acc[i][j]);
        }
        __syncthreads();
    }
    #pragma unroll
    for (int i = 0; i < 8; i++) {
        int gm = m0 + tm + i;
        if (gm < NN) {
            *(float4*)&g_h1[(size_t)gm * F1 + tn]     = make_float4(acc[i][0], acc[i][1], acc[i][2], acc[i][3]);
            *(float4*)&g_h1[(size_t)gm * F1 + tn + 4] = make_float4(acc[i][4], acc[i][5], acc[i][6], acc[i][7]);
        }
    }
}

// ---------------- attention dot products, layer 1 ----------------
// one thread per (node, head); grid 1250 x 320 == NN*H1n exactly
__global__ void k_att1(const float* __restrict__ att_src, const float* __restrict__ att_dst) {
    int gid = blockIdx.x * blockDim.x + threadIdx.x;   // 0..399999
    int n = gid >> 3, h = gid & 7;
    const float* hp = &g_h1[(size_t)n * F1 + h * C1n];
    float s = 0.f, d = 0.f;
    #pragma unroll
    for (int c = 0; c < C1n; c++) {
        float v = hp[c];
        s = fmaf(v, att_src[h * C1n + c], s);
        d = fmaf(v, att_dst[h * C1n + c], d);
    }
    g_as1[n * H1n + h] = s;
    g_ad1[n * H1n + h] = d;
}

// ---------------- aggregation layer 1 (+bias, ELU) ----------------
// one thread per (node, head), 16 channels in registers; 1250 x 320 exact
__global__ void k_agg1(const float* __restrict__ b1) {
    int gid = blockIdx.x * blockDim.x + threadIdx.x;
    int n = gid >> 3, h = gid & 7;
    int beg = g_rowptr[n], end = g_rowptr[n + 1];
    float adn = g_ad1[n * H1n + h];

    float m = -INFINITY;
    for (int j = beg; j < end; j++) {
        int s = g_col[j];
        float e = g_as1[s * H1n + h] + adn;
        e = (e > 0.f) ? e : NEG_SLOPE * e;
        m = fmaxf(m, e);
    }
    float denom = 0.f;
    float acc[C1n];
    #pragma unroll
    for (int c = 0; c < C1n; c++) acc[c] = 0.f;
    for (int j = beg; j < end; j++) {
        int s = g_col[j];
        float e = g_as1[s * H1n + h] + adn;
        e = (e > 0.f) ? e : NEG_SLOPE * e;
        float ex = __expf(e - m);
        denom += ex;
        const float4* hp = (const float4*)&g_h1[(size_t)s * F1 + h * C1n];
        #pragma unroll
        for (int q = 0; q < 4; q++) {
            float4 v = hp[q];
            acc[q * 4 + 0] = fmaf(ex, v.x, acc[q * 4 + 0]);
            acc[q * 4 + 1] = fmaf(ex, v.y, acc[q * 4 + 1]);
            acc[q * 4 + 2] = fmaf(ex, v.z, acc[q * 4 + 2]);
            acc[q * 4 + 3] = fmaf(ex, v.w, acc[q * 4 + 3]);
        }
    }
    float inv = 1.f / (denom + 1e-16f);
    float* op = &g_h1b[(size_t)n * F1 + h * C1n];
    #pragma unroll
    for (int c = 0; c < C1n; c++) {
        float v = acc[c] * inv + b1[h * C1n + c];
        v = (v > 0.f) ? v : (__expf(v) - 1.f);    // ELU
        op[c] = v;
    }
}

// ---------------- GEMM2: h2 = h1b @ W2  (50000x128 @ 128x40) ----------------
// block = (40, 8): 8 nodes per block, 6250 blocks exact
__global__ void k_gemm2(const float* __restrict__ W2) {
    __shared__ float Ws[128 * 40];
    __shared__ float hs[8][128];
    int tid = threadIdx.y * 40 + threadIdx.x;   // 0..319
    for (int i = tid; i < 128 * 40; i += 320) Ws[i] = W2[i];
    int n0 = blockIdx.x * 8;
    for (int i = tid; i < 8 * 128; i += 320) {
        int r = i >> 7, c = i & 127;
        hs[r][c] = g_h1b[(size_t)(n0 + r) * F1 + c];
    }
    __syncthreads();
    int c = threadIdx.x, r = threadIdx.y;
    float acc = 0.f;
    #pragma unroll 8
    for (int k = 0; k < 128; k++)
        acc = fmaf(hs[r][k], Ws[k * 40 + c], acc);
    g_h2[(size_t)(n0 + r) * F2 + c] = acc;
}

// ---------------- attention dot products, layer 2 ----------------
__global__ void k_att2(const float* __restrict__ att_src, const float* __restrict__ att_dst) {
    int n = blockIdx.x * blockDim.x + threadIdx.x;
    if (n >= NN) return;
    const float* hp = &g_h2[(size_t)n * F2];
    float s = 0.f, d = 0.f;
    #pragma unroll
    for (int c = 0; c < F2; c++) {
        float v = hp[c];
        s = fmaf(v, att_src[c], s);
        d = fmaf(v, att_dst[c], d);
    }
    g_as2[n] = s;
    g_ad2[n] = d;
}

// ---------------- aggregation layer 2 (+bias, log_softmax) ----------------
// 8 threads per node, 5 channels each; 1250 x 320 exact, no early exits
__global__ void k_agg2(const float* __restrict__ b2, float* __restrict__ out) {
    int gid = blockIdx.x * blockDim.x + threadIdx.x;
    int n = gid >> 3, th = gid & 7;
    int beg = g_rowptr[n], end = g_rowptr[n + 1];
    float adn = g_ad2[n];

    float m = -INFINITY;
    for (int j = beg; j < end; j++) {
        float e = g_as2[g_col[j]] + adn;
        e = (e > 0.f) ? e : NEG_SLOPE * e;
        m = fmaxf(m, e);
    }
    float denom = 0.f;
    float acc[5] = {0.f, 0.f, 0.f, 0.f, 0.f};
    for (int j = beg; j < end; j++) {
        int s = g_col[j];
        float e = g_as2[s] + adn;
        e = (e > 0.f) ? e : NEG_SLOPE * e;
        float ex = __expf(e - m);
        denom += ex;
        const float* hp = &g_h2[(size_t)s * F2 + th * 5];
        #pragma unroll
        for (int q = 0; q < 5; q++) acc[q] = fmaf(ex, hp[q], acc[q]);
    }
    float inv = 1.f / (denom + 1e-16f);
    float val[5];
    #pragma unroll
    for (int q = 0; q < 5; q++) val[q] = acc[q] * inv + b2[th * 5 + q];

    // log_softmax over the 40 classes spread across 8 aligned lanes
    float lm = val[0];
    #pragma unroll
    for (int q = 1; q < 5; q++) lm = fmaxf(lm, val[q]);
    #pragma unroll
    for (int o = 1; o < 8; o <<= 1)
        lm = fmaxf(lm, __shfl_xor_sync(0xffffffffu, lm, o));
    float se = 0.f;
    #pragma unroll
    for (int q = 0; q < 5; q++) se += __expf(val[q] - lm);
    #pragma unroll
    for (int o = 1; o < 8; o <<= 1)
        se += __shfl_xor_sync(0xffffffffu, se, o);
    float lse = lm + logf(se);
    float* op = &out[(size_t)n * F2 + th * 5];
    #pragma unroll
    for (int q = 0; q < 5; q++) op[q] = val[q] - lse;
}

// ---------------- launch ----------------
extern "C" void kernel_launch(void* const* d_in, const int* in_sizes, int n_in,
                              void* d_out, int out_size) {
    const float* x    = (const float*)d_in[0];
    const void*  ei   = d_in[1];              // int32 or int64, probed on device
    const float* W1   = (const float*)d_in[2];
    const float* as1  = (const float*)d_in[3];
    const float* ad1  = (const float*)d_in[4];
    const float* b1   = (const float*)d_in[5];
    const float* W2   = (const float*)d_in[6];
    const float* as2  = (const float*)d_in[7];
    const float* ad2  = (const float*)d_in[8];
    const float* b2   = (const float*)d_in[9];
    float* out = (float*)d_out;

    // CSR by destination (rebuilt every call; value-independent)
    k_detect <<<1, 32>>>(ei);
    k_zero_deg<<<(NN + 255) / 256, 256>>>();
    k_hist   <<<(ET + 255) / 256, 256>>>(ei);
    k_scan   <<<1, 1024>>>();
    k_scatter<<<(ET + 255) / 256, 256>>>(ei);

    // layer 1
    k_gemm1<<<(NN + 127) / 128, 256>>>(x, W1);
    k_att1 <<<1250, 320>>>(as1, ad1);
    k_agg1 <<<1250, 320>>>(b1);

    // layer 2
    k_gemm2<<<6250, dim3(40, 8)>>>(W2);
    k_att2 <<<(NN + 255) / 256, 256>>>(as2, ad2);
    k_agg2 <<<1250, 320>>>(b2, out);
}

// round 10
// speedup vs baseline: 1.4199x; 1.4199x over previous
#include <cuda_runtime.h>
#include <cuda_bf16.h>
#include <math.h>
#include <stdint.h>

#define NN 50000
#define EE 800000
#define ET 850000          // edges + self loops
#define F_IN 512
#define F1 128             // H1*C1
#define H1n 8
#define C1n 16
#define F2 40              // H2*C2 = num classes
#define NEG_SLOPE 0.2f
#define NB1 196            // ceil(NN/256)

// ---------------- static scratch (no allocation allowed) ----------------
__device__ float g_h1 [(size_t)NN * F1];   // x@W1
__device__ float g_h1b[(size_t)NN * F1];   // elu(layer1 out)
__device__ float g_h2 [(size_t)NN * F2];   // h1b@W2
__device__ float g_as1[NN * H1n], g_ad1[NN * H1n];
__device__ float g_as2[NN],        g_ad2[NN];
__device__ int   g_deg[NN], g_fill[NN];
__device__ int   g_rowptr[NN + 1];
__device__ int   g_col[ET];
__device__ int   g_is64;               // 1 if edge_index is int64, 0 if int32
__device__ int   g_bsum[256], g_boff[256];
__device__ uint32_t g_w1t_h[128 * 256];  // W1^T as bf16x2 pairs (n-major), hi part
__device__ uint32_t g_w1t_l[128 * 256];  // lo part

__device__ __forceinline__ uint32_t pack_bf2(__nv_bfloat16 x, __nv_bfloat16 y) {
    __nv_bfloat162 t; t.x = x; t.y = y;
    return *reinterpret_cast<uint32_t*>(&t);
}

// mma.sync m16n8k16 row.col bf16 -> fp32 accumulate (in place)
__device__ __forceinline__ void mma16816(float* d, const uint32_t* a, const uint32_t* b) {
    asm volatile(
        "mma.sync.aligned.m16n8k16.row.col.f32.bf16.bf16.f32 "
        "{%0,%1,%2,%3}, {%4,%5,%6,%7}, {%8,%9}, {%0,%1,%2,%3};"
        : "+f"(d[0]), "+f"(d[1]), "+f"(d[2]), "+f"(d[3])
        : "r"(a[0]), "r"(a[1]), "r"(a[2]), "r"(a[3]), "r"(b[0]), "r"(b[1]));
}

// ---------------- dtype probe ----------------
__global__ void k_detect(const void* __restrict__ ei) {
    if (threadIdx.x != 0 || blockIdx.x != 0) return;
    const unsigned long long* p = (const unsigned long long*)ei;
    int is64 = 1;
    for (int i = 0; i < 256; i++)
        if (p[i] >= (unsigned long long)NN) { is64 = 0; break; }
    g_is64 = is64;
}
__device__ __forceinline__ int load_idx(const void* ei, int i) {
    if (g_is64) return (int)((const long long*)ei)[i];
    return ((const int*)ei)[i];
}

// ---------------- CSR build ----------------
__global__ void k_zero_deg() {
    int i = blockIdx.x * blockDim.x + threadIdx.x;
    if (i < NN) g_deg[i] = 0;
}
__global__ void k_hist(const void* __restrict__ ei) {
    int e = blockIdx.x * blockDim.x + threadIdx.x;
    if (e >= ET) return;
    int d;
    if (e < EE) d = load_idx(ei, EE + e);
    else        d = e - EE;
    atomicAdd(&g_deg[d], 1);
}
// 3-level scan of g_deg -> g_rowptr
__global__ void k_scan_l1() {
    __shared__ int sh[256];
    int t = threadIdx.x, i = blockIdx.x * 256 + t;
    sh[t] = (i < NN) ? g_deg[i] : 0;
    __syncthreads();
    for (int o = 128; o > 0; o >>= 1) { if (t < o) sh[t] += sh[t + o]; __syncthreads(); }
    if (t == 0) g_bsum[blockIdx.x] = sh[0];
}
__global__ void k_scan_l2() {
    __shared__ int sh[256];
    int t = threadIdx.x;
    int v = (t < NB1) ? g_bsum[t] : 0;
    sh[t] = v;
    __syncthreads();
    for (int o = 1; o < 256; o <<= 1) {
        int u = (t >= o) ? sh[t - o] : 0;
        __syncthreads(); sh[t] += u; __syncthreads();
    }
    if (t < NB1) g_boff[t] = sh[t] - v;
    if (t == 255) g_rowptr[NN] = sh[255];
}
__global__ void k_scan_l3() {
    __shared__ int sh[256];
    int t = threadIdx.x, i = blockIdx.x * 256 + t;
    int v = (i < NN) ? g_deg[i] : 0;
    sh[t] = v;
    __syncthreads();
    for (int o = 1; o < 256; o <<= 1) {
        int u = (t >= o) ? sh[t - o] : 0;
        __syncthreads(); sh[t] += u; __syncthreads();
    }
    if (i < NN) { g_rowptr[i] = g_boff[blockIdx.x] + sh[t] - v; g_fill[i] = 0; }
}
__global__ void k_scatter(const void* __restrict__ ei) {
    int e = blockIdx.x * blockDim.x + threadIdx.x;
    if (e >= ET) return;
    int s, d;
    if (e < EE) { s = load_idx(ei, e); d = load_idx(ei, EE + e); }
    else        { s = d = e - EE; }
    int pos = g_rowptr[d] + atomicAdd(&g_fill[d], 1);
    g_col[pos] = s;
}

// ---------------- W1^T fp32 -> bf16 hi/lo split ----------------
__global__ void k_cvt_w(const float* __restrict__ W1) {
    int idx = blockIdx.x * 256 + threadIdx.x;   // 128*256
    if (idx >= 128 * 256) return;
    int n = idx >> 8, p = idx & 255;
    int k0 = p * 2;
    float a = W1[(size_t)k0 * F1 + n];
    float b = W1[(size_t)(k0 + 1) * F1 + n];
    __nv_bfloat16 ah = __float2bfloat16(a), bh = __float2bfloat16(b);
    __nv_bfloat16 al = __float2bfloat16(a - __bfloat162float(ah));
    __nv_bfloat16 bl = __float2bfloat16(b - __bfloat162float(bh));
    g_w1t_h[idx] = pack_bf2(ah, bh);
    g_w1t_l[idx] = pack_bf2(al, bl);
}

// ---------------- GEMM1 via HMMA: h1 = x @ W1 (bf16 hi/lo split) -----------
// CTA: 128 rows x 128 cols, 256 threads = 8 warps (2x4), warp tile 64x32.
// BK=32. A converted fp32->bf16 hi/lo in flight. 3 MMAs per tile pair:
// Ah*Bh + Ah*Bl + Al*Bh (Al*Bl term ~2^-16, dropped).
#define SPAD 20   // smem row stride in uint32 (conflict-free for frag loads)
__global__ void __launch_bounds__(256)
k_gemm1_mma(const float* __restrict__ x) {
    __shared__ uint32_t As_h[128 * SPAD];
    __shared__ uint32_t As_l[128 * SPAD];
    __shared__ uint32_t Bs_h[128 * SPAD];
    __shared__ uint32_t Bs_l[128 * SPAD];

    const int tid = threadIdx.x;
    const int wid = tid >> 5, lid = tid & 31;
    const int wm = (wid >> 2) * 64;        // warp m offset (0 or 64)
    const int wn = (wid & 3) * 32;         // warp n offset
    const int g4 = lid >> 2;               // group id 0..7
    const int t4 = lid & 3;                // 0..3
    const int m0 = blockIdx.x * 128;

    float c[4][4][4];
    #pragma unroll
    for (int mi = 0; mi < 4; mi++)
        #pragma unroll
        for (int ni = 0; ni < 4; ni++)
            #pragma unroll
            for (int q = 0; q < 4; q++) c[mi][ni][q] = 0.f;

    for (int kk = 0; kk < F_IN; kk += 32) {
        // load A chunk: 128 rows x 16 uint32 (32 bf16), convert fp32->hi/lo
        #pragma unroll
        for (int i = 0; i < 8; i++) {
            int li = tid + i * 256;        // 0..2047
            int row = li >> 4, k2 = li & 15;
            int gr = m0 + row;
            float2 v = make_float2(0.f, 0.f);
            if (gr < NN) v = *(const float2*)&x[(size_t)gr * F_IN + kk + k2 * 2];
            __nv_bfloat16 h0 = __float2bfloat16(v.x), h1 = __float2bfloat16(v.y);
            __nv_bfloat16 l0 = __float2bfloat16(v.x - __bfloat162float(h0));
            __nv_bfloat16 l1 = __float2bfloat16(v.y - __bfloat162float(h1));
            As_h[row * SPAD + k2] = pack_bf2(h0, h1);
            As_l[row * SPAD + k2] = pack_bf2(l0, l1);
        }
        // load B chunk: 128 n-rows x 16 uint32
        #pragma unroll
        for (int i = 0; i < 8; i++) {
            int li = tid + i * 256;
            int n = li >> 4, k2 = li & 15;
            int src = n * 256 + (kk >> 1) + k2;
            Bs_h[n * SPAD + k2] = g_w1t_h[src];
            Bs_l[n * SPAD + k2] = g_w1t_l[src];
        }
        __syncthreads();

        #pragma unroll
        for (int ks = 0; ks < 2; ks++) {
            const int ko = ks * 8;
            uint32_t ah[4][4], al[4][4];
            #pragma unroll
            for (int mi = 0; mi < 4; mi++) {
                int r0 = (wm + mi * 16 + g4) * SPAD;
                int r8 = r0 + 8 * SPAD;
                ah[mi][0] = As_h[r0 + ko + t4];
                ah[mi][1] = As_h[r8 + ko + t4];
                ah[mi][2] = As_h[r0 + ko + t4 + 4];
                ah[mi][3] = As_h[r8 + ko + t4 + 4];
                al[mi][0] = As_l[r0 + ko + t4];
                al[mi][1] = As_l[r8 + ko + t4];
                al[mi][2] = As_l[r0 + ko + t4 + 4];
                al[mi][3] = As_l[r8 + ko + t4 + 4];
            }
            uint32_t bh[4][2], bl[4][2];
            #pragma unroll
            for (int ni = 0; ni < 4; ni++) {
                int nr = (wn + ni * 8 + g4) * SPAD;
                bh[ni][0] = Bs_h[nr + ko + t4];
                bh[ni][1] = Bs_h[nr + ko + t4 + 4];
                bl[ni][0] = Bs_l[nr + ko + t4];
                bl[ni][1] = Bs_l[nr + ko + t4 + 4];
            }
            #pragma unroll
            for (int mi = 0; mi < 4; mi++)
                #pragma unroll
                for (int ni = 0; ni < 4; ni++) {
                    mma16816(c[mi][ni], ah[mi], bh[ni]);
                    mma16816(c[mi][ni], ah[mi], bl[ni]);
                    mma16816(c[mi][ni], al[mi], bh[ni]);
                }
        }
        __syncthreads();
    }

    // epilogue: c frag layout: rows g4 / g4+8, cols t4*2, t4*2+1
    #pragma unroll
    for (int mi = 0; mi < 4; mi++) {
        int r0 = m0 + wm + mi * 16 + g4;
        int r1 = r0 + 8;
        #pragma unroll
        for (int ni = 0; ni < 4; ni++) {
            int col = wn + ni * 8 + t4 * 2;
            if (r0 < NN)
                *(float2*)&g_h1[(size_t)r0 * F1 + col] = make_float2(c[mi][ni][0], c[mi][ni][1]);
            if (r1 < NN)
                *(float2*)&g_h1[(size_t)r1 * F1 + col] = make_float2(c[mi][ni][2], c[mi][ni][3]);
        }
    }
}

// ---------------- attention dot products, layer 1 ----------------
__global__ void k_att1(const float* __restrict__ att_src, const float* __restrict__ att_dst) {
    int gid = blockIdx.x * blockDim.x + threadIdx.x;   // 0..399999
    int n = gid >> 3, h = gid & 7;
    const float* hp = &g_h1[(size_t)n * F1 + h * C1n];
    float s = 0.f, d = 0.f;
    #pragma unroll
    for (int c = 0; c < C1n; c++) {
        float v = hp[c];
        s = fmaf(v, att_src[h * C1n + c], s);
        d = fmaf(v, att_dst[h * C1n + c], d);
    }
    g_as1[n * H1n + h] = s;
    g_ad1[n * H1n + h] = d;
}

// ---------------- aggregation layer 1 (+bias, ELU) ----------------
__global__ void k_agg1(const float* __restrict__ b1) {
    int gid = blockIdx.x * blockDim.x + threadIdx.x;
    int n = gid >> 3, h = gid & 7;
    int beg = g_rowptr[n], end = g_rowptr[n + 1];
    float adn = g_ad1[n * H1n + h];

    float m = -INFINITY;
    for (int j = beg; j < end; j++) {
        int s = g_col[j];
        float e = g_as1[s * H1n + h] + adn;
        e = (e > 0.f) ? e : NEG_SLOPE * e;
        m = fmaxf(m, e);
    }
    float denom = 0.f;
    float acc[C1n];
    #pragma unroll
    for (int c = 0; c < C1n; c++) acc[c] = 0.f;
    for (int j = beg; j < end; j++) {
        int s = g_col[j];
        float e = g_as1[s * H1n + h] + adn;
        e = (e > 0.f) ? e : NEG_SLOPE * e;
        float ex = __expf(e - m);
        denom += ex;
        const float4* hp = (const float4*)&g_h1[(size_t)s * F1 + h * C1n];
        #pragma unroll
        for (int q = 0; q < 4; q++) {
            float4 v = hp[q];
            acc[q * 4 + 0] = fmaf(ex, v.x, acc[q * 4 + 0]);
            acc[q * 4 + 1] = fmaf(ex, v.y, acc[q * 4 + 1]);
            acc[q * 4 + 2] = fmaf(ex, v.z, acc[q * 4 + 2]);
            acc[q * 4 + 3] = fmaf(ex, v.w, acc[q * 4 + 3]);
        }
    }
    float inv = 1.f / (denom + 1e-16f);
    float* op = &g_h1b[(size_t)n * F1 + h * C1n];
    #pragma unroll
    for (int c = 0; c < C1n; c++) {
        float v = acc[c] * inv + b1[h * C1n + c];
        v = (v > 0.f) ? v : (__expf(v) - 1.f);    // ELU
        op[c] = v;
    }
}

// ---------------- GEMM2: h2 = h1b @ W2  (50000x128 @ 128x40) ----------------
__global__ void k_gemm2(const float* __restrict__ W2) {
    __shared__ float Ws[128 * 40];
    __shared__ float hs[8][128];
    int tid = threadIdx.y * 40 + threadIdx.x;
    for (int i = tid; i < 128 * 40; i += 320) Ws[i] = W2[i];
    int n0 = blockIdx.x * 8;
    for (int i = tid; i < 8 * 128; i += 320) {
        int r = i >> 7, c = i & 127;
        hs[r][c] = g_h1b[(size_t)(n0 + r) * F1 + c];
    }
    __syncthreads();
    int c = threadIdx.x, r = threadIdx.y;
    float acc = 0.f;
    #pragma unroll 8
    for (int k = 0; k < 128; k++)
        acc = fmaf(hs[r][k], Ws[k * 40 + c], acc);
    g_h2[(size_t)(n0 + r) * F2 + c] = acc;
}

// ---------------- attention dot products, layer 2 ----------------
__global__ void k_att2(const float* __restrict__ att_src, const float* __restrict__ att_dst) {
    int n = blockIdx.x * blockDim.x + threadIdx.x;
    if (n >= NN) return;
    const float* hp = &g_h2[(size_t)n * F2];
    float s = 0.f, d = 0.f;
    #pragma unroll
    for (int c = 0; c < F2; c++) {
        float v = hp[c];
        s = fmaf(v, att_src[c], s);
        d = fmaf(v, att_dst[c], d);
    }
    g_as2[n] = s;
    g_ad2[n] = d;
}

// ---------------- aggregation layer 2 (+bias, log_softmax) ----------------
__global__ void k_agg2(const float* __restrict__ b2, float* __restrict__ out) {
    int gid = blockIdx.x * blockDim.x + threadIdx.x;
    int n = gid >> 3, th = gid & 7;
    int beg = g_rowptr[n], end = g_rowptr[n + 1];
    float adn = g_ad2[n];

    float m = -INFINITY;
    for (int j = beg; j < end; j++) {
        float e = g_as2[g_col[j]] + adn;
        e = (e > 0.f) ? e : NEG_SLOPE * e;
        m = fmaxf(m, e);
    }
    float denom = 0.f;
    float acc[5] = {0.f, 0.f, 0.f, 0.f, 0.f};
    for (int j = beg; j < end; j++) {
        int s = g_col[j];
        float e = g_as2[s] + adn;
        e = (e > 0.f) ? e : NEG_SLOPE * e;
        float ex = __expf(e - m);
        denom += ex;
        const float* hp = &g_h2[(size_t)s * F2 + th * 5];
        #pragma unroll
        for (int q = 0; q < 5; q++) acc[q] = fmaf(ex, hp[q], acc[q]);
    }
    float inv = 1.f / (denom + 1e-16f);
    float val[5];
    #pragma unroll
    for (int q = 0; q < 5; q++) val[q] = acc[q] * inv + b2[th * 5 + q];

    float lm = val[0];
    #pragma unroll
    for (int q = 1; q < 5; q++) lm = fmaxf(lm, val[q]);
    #pragma unroll
    for (int o = 1; o < 8; o <<= 1)
        lm = fmaxf(lm, __shfl_xor_sync(0xffffffffu, lm, o));
    float se = 0.f;
    #pragma unroll
    for (int q = 0; q < 5; q++) se += __expf(val[q] - lm);
    #pragma unroll
    for (int o = 1; o < 8; o <<= 1)
        se += __shfl_xor_sync(0xffffffffu, se, o);
    float lse = lm + logf(se);
    float* op = &out[(size_t)n * F2 + th * 5];
    #pragma unroll
    for (int q = 0; q < 5; q++) op[q] = val[q] - lse;
}

// ---------------- launch ----------------
extern "C" void kernel_launch(void* const* d_in, const int* in_sizes, int n_in,
                              void* d_out, int out_size) {
    const float* x    = (const float*)d_in[0];
    const void*  ei   = d_in[1];
    const float* W1   = (const float*)d_in[2];
    const float* as1  = (const float*)d_in[3];
    const float* ad1  = (const float*)d_in[4];
    const float* b1   = (const float*)d_in[5];
    const float* W2   = (const float*)d_in[6];
    const float* as2  = (const float*)d_in[7];
    const float* ad2  = (const float*)d_in[8];
    const float* b2   = (const float*)d_in[9];
    float* out = (float*)d_out;

    // CSR by destination
    k_detect  <<<1, 32>>>(ei);
    k_zero_deg<<<NB1, 256>>>();
    k_hist    <<<(ET + 255) / 256, 256>>>(ei);
    k_scan_l1 <<<NB1, 256>>>();
    k_scan_l2 <<<1, 256>>>();
    k_scan_l3 <<<NB1, 256>>>();
    k_scatter <<<(ET + 255) / 256, 256>>>(ei);

    // layer 1
    k_cvt_w    <<<128, 256>>>(W1);
    k_gemm1_mma<<<391, 256>>>(x);
    k_att1     <<<1250, 320>>>(as1, ad1);
    k_agg1     <<<1250, 320>>>(b1);

    // layer 2
    k_gemm2<<<6250, dim3(40, 8)>>>(W2);
    k_att2 <<<(NN + 255) / 256, 256>>>(as2, ad2);
    k_agg2 <<<1250, 320>>>(b2, out);
}